// round 3
// baseline (speedup 1.0000x reference)
#include <cuda_runtime.h>
#include <math.h>
#include <stdint.h>

// Problem dims (fixed by the dataset)
#define BB 32
#define DD 1024
#define HH 1024

#define GEMM_BLOCKS 32        // h-tiles of 32: 1024/32
#define STREAM_BLOCKS 1024
#define NTHREADS 256

// d_out layout (float32, reference return order):
//   out   [B,H]      @ 0
//   u_new [B,H]      @ 32768
//   E_w   [B,D,H]    @ 65536
//   E_b   [B,H]      @ 65536 + 33554432
#define OFF_UNEW (BB*HH)
#define OFF_EW   (2*BB*HH)
#define OFF_EB   (2*BB*HH + BB*DD*HH)

// stream pipeline: per block one contiguous chunk of 8192 float4 (128KB),
// 16 stages of 512 float4 (8KB), double-buffered cp.async
#define STAGE_F4 512
#define NSTAGES 16
#define CHUNK_F4 (STAGE_F4 * NSTAGES)   // 8192; N4 = 2^23 -> exactly 1024 chunks

__device__ __forceinline__ uint32_t smem_u32(const void* p) {
    return (uint32_t)__cvta_generic_to_shared(p);
}

__global__ void __launch_bounds__(NTHREADS, 8)
diag_rtrl_fused_kernel(
    const float* __restrict__ x,   // [B,D]
    const float* __restrict__ w,   // [D,H]
    const float* __restrict__ b,   // [H]
    const float* __restrict__ u,   // [B,H]
    const float* __restrict__ Ew,  // [1,B,D,H]
    const float* __restrict__ Eb,  // [1,B,H]
    float* __restrict__ out)       // packed outputs
{
    // one aliased static smem region: stream uses 16KB (2 x 8KB stages),
    // GEMM uses 12.3KB (xs 32x33 + ws 32x32)
    __shared__ __align__(16) unsigned char smem_raw[16384];

    if (blockIdx.x >= GEMM_BLOCKS) {
        // ---------------- E_w streaming path (cp.async double buffer) ----
        // E_new_w[i,d,h] = 0.9*E_w[i,d,h] + x[i,d]; float4 idx p -> x[p>>8]
        const int t    = threadIdx.x;
        const int base = (blockIdx.x - GEMM_BLOCKS) * CHUNK_F4;
        const float4* __restrict__ gin =
            reinterpret_cast<const float4*>(Ew) + base;
        float4* __restrict__ gout =
            reinterpret_cast<float4*>(&out[OFF_EW]) + base;
        const float4* sbuf = reinterpret_cast<const float4*>(smem_raw);
        const uint32_t saddr = smem_u32(smem_raw);

        // prefetch stage 0 into buffer 0 (each thread: 2 x 16B cp.async)
        {
            const float4* src = gin + t * 2;
            uint32_t dst = saddr + t * 32;
            asm volatile("cp.async.cg.shared.global [%0], [%1], 16;"
                         :: "r"(dst), "l"(src));
            asm volatile("cp.async.cg.shared.global [%0], [%1], 16;"
                         :: "r"(dst + 16), "l"(src + 1));
            asm volatile("cp.async.commit_group;");
        }

        #pragma unroll 1
        for (int s = 0; s < NSTAGES; s++) {
            // prefetch stage s+1 into the other buffer
            if (s + 1 < NSTAGES) {
                const float4* src = gin + (s + 1) * STAGE_F4 + t * 2;
                uint32_t dst = saddr + ((s + 1) & 1) * 8192 + t * 32;
                asm volatile("cp.async.cg.shared.global [%0], [%1], 16;"
                             :: "r"(dst), "l"(src));
                asm volatile("cp.async.cg.shared.global [%0], [%1], 16;"
                             :: "r"(dst + 16), "l"(src + 1));
            }
            asm volatile("cp.async.commit_group;");
            // all groups except the newest complete -> stage s is resident
            asm volatile("cp.async.wait_group 1;");
            __syncthreads();

            #pragma unroll
            for (int j = 0; j < 2; j++) {
                const int pl = s * STAGE_F4 + t * 2 + j;   // local float4 idx
                float4 e = sbuf[(s & 1) * 512 + t * 2 + j];
                float xv = __ldg(&x[(base + pl) >> 8]);
                float4 r;
                r.x = fmaf(0.9f, e.x, xv);
                r.y = fmaf(0.9f, e.y, xv);
                r.z = fmaf(0.9f, e.z, xv);
                r.w = fmaf(0.9f, e.w, xv);
                __stcs(gout + pl, r);
            }
            __syncthreads();  // buffer (s&1) free for refill at iter s+1
        }
    } else {
        // ---------------- GEMM + epilogue path ----------------
        // block handles h-tile of 32 columns, all 32 batch rows.
        float* xs = reinterpret_cast<float*>(smem_raw);           // [32][33]
        float* ws = reinterpret_cast<float*>(smem_raw + 4224);    // [32][32]

        const int t  = threadIdx.x;
        const int h0 = blockIdx.x * 32;
        const int hx = t & 7;           // which float4 of the 32-h tile
        const int i  = t >> 3;          // batch row 0..31

        float4 acc = make_float4(0.f, 0.f, 0.f, 0.f);

        for (int kt = 0; kt < DD; kt += 32) {
            // x tile: 32 rows x 32 k (coalesced)
            for (int m = t; m < 1024; m += NTHREADS)
                xs[(m >> 5) * 33 + (m & 31)] = x[(m >> 5) * DD + kt + (m & 31)];
            // w tile: 32 k x 32 h (coalesced)
            for (int m = t; m < 1024; m += NTHREADS)
                ws[m] = w[(kt + (m >> 5)) * HH + h0 + (m & 31)];
            __syncthreads();

            #pragma unroll 8
            for (int k = 0; k < 32; k++) {
                float4 wv = reinterpret_cast<const float4*>(&ws[k * 32])[hx];
                float xv = xs[i * 33 + k];
                acc.x = fmaf(xv, wv.x, acc.x);
                acc.y = fmaf(xv, wv.y, acc.y);
                acc.z = fmaf(xv, wv.z, acc.z);
                acc.w = fmaf(xv, wv.w, acc.w);
            }
            __syncthreads();
        }

        // epilogue: z = 0.9*u + x@w + b ; out = tanh(z); u_new = z; E_b
        const int h   = h0 + hx * 4;
        const int idx = i * HH + h;
        float4 bv = *reinterpret_cast<const float4*>(&b[h]);
        float4 uv = *reinterpret_cast<const float4*>(&u[idx]);
        float4 z;
        z.x = fmaf(0.9f, uv.x, acc.x + bv.x);
        z.y = fmaf(0.9f, uv.y, acc.y + bv.y);
        z.z = fmaf(0.9f, uv.z, acc.z + bv.z);
        z.w = fmaf(0.9f, uv.w, acc.w + bv.w);

        *reinterpret_cast<float4*>(&out[OFF_UNEW + idx]) = z;

        float4 o;
        o.x = tanhf(z.x); o.y = tanhf(z.y);
        o.z = tanhf(z.z); o.w = tanhf(z.w);
        *reinterpret_cast<float4*>(&out[idx]) = o;

        float4 ev = *reinterpret_cast<const float4*>(&Eb[idx]);
        float4 e;
        e.x = fmaf(0.9f, ev.x, 1.0f);
        e.y = fmaf(0.9f, ev.y, 1.0f);
        e.z = fmaf(0.9f, ev.z, 1.0f);
        e.w = fmaf(0.9f, ev.w, 1.0f);
        *reinterpret_cast<float4*>(&out[OFF_EB + idx]) = e;
    }
}

extern "C" void kernel_launch(void* const* d_in, const int* in_sizes, int n_in,
                              void* d_out, int out_size) {
    const float* x  = (const float*)d_in[0];  // [32,1024]
    const float* w  = (const float*)d_in[1];  // [1024,1024]
    const float* b  = (const float*)d_in[2];  // [1024]
    const float* u  = (const float*)d_in[3];  // [32,1024]
    const float* Ew = (const float*)d_in[4];  // [1,32,1024,1024]
    const float* Eb = (const float*)d_in[5];  // [1,32,1024]
    float* out = (float*)d_out;

    diag_rtrl_fused_kernel<<<GEMM_BLOCKS + STREAM_BLOCKS, NTHREADS>>>(
        x, w, b, u, Ew, Eb, out);
}

// round 4
// speedup vs baseline: 1.5746x; 1.5746x over previous
#include <cuda_runtime.h>
#include <math.h>

// Problem dims (fixed by the dataset)
#define BB 32
#define DD 1024
#define HH 1024

#define GEMM_BLOCKS 32        // h-tiles of 32: 1024/32
#define STREAM_BLOCKS 856     // 32 + 856 = 888 = 148 SMs * 6 blocks -> single wave
#define NTHREADS 256
#define N4 ((BB*DD*HH)/4)     // 8388608 float4

// d_out layout (float32, reference return order):
//   out   [B,H]      @ 0
//   u_new [B,H]      @ 32768
//   E_w   [B,D,H]    @ 65536
//   E_b   [B,H]      @ 65536 + 33554432
#define OFF_UNEW (BB*HH)
#define OFF_EW   (2*BB*HH)
#define OFF_EB   (2*BB*HH + BB*DD*HH)

__global__ void __launch_bounds__(NTHREADS, 6)
diag_rtrl_fused_kernel(
    const float* __restrict__ x,   // [B,D]
    const float* __restrict__ w,   // [D,H]
    const float* __restrict__ b,   // [H]
    const float* __restrict__ u,   // [B,H]
    const float* __restrict__ Ew,  // [1,B,D,H]
    const float* __restrict__ Eb,  // [1,B,H]
    float* __restrict__ out)       // packed outputs
{
    if (blockIdx.x >= GEMM_BLOCKS) {
        // ---------------- E_w streaming path ----------------
        // E_new_w[i,d,h] = 0.9*E_w[i,d,h] + x[i,d]
        // float4 index p -> element 4p -> x index (4p)>>10 = p>>8
        const float4* __restrict__ ein = reinterpret_cast<const float4*>(Ew);
        float4* __restrict__ eo = reinterpret_cast<float4*>(&out[OFF_EW]);

        const int stride = STREAM_BLOCKS * NTHREADS;   // 219136
        int p = (blockIdx.x - GEMM_BLOCKS) * NTHREADS + threadIdx.x;

        // unroll x2: two independent front-batched loads per iteration
        #pragma unroll 1
        for (; p + stride < N4; p += 2 * stride) {
            const int q = p + stride;
            float4 e0 = __ldcs(ein + p);
            float4 e1 = __ldcs(ein + q);
            float x0 = __ldg(&x[p >> 8]);
            float x1 = __ldg(&x[q >> 8]);

            float4 r0, r1;
            r0.x = fmaf(0.9f, e0.x, x0); r0.y = fmaf(0.9f, e0.y, x0);
            r0.z = fmaf(0.9f, e0.z, x0); r0.w = fmaf(0.9f, e0.w, x0);
            r1.x = fmaf(0.9f, e1.x, x1); r1.y = fmaf(0.9f, e1.y, x1);
            r1.z = fmaf(0.9f, e1.z, x1); r1.w = fmaf(0.9f, e1.w, x1);

            __stcs(eo + p, r0);
            __stcs(eo + q, r1);
        }
        if (p < N4) {
            float4 e = __ldcs(ein + p);
            float xv = __ldg(&x[p >> 8]);
            float4 r;
            r.x = fmaf(0.9f, e.x, xv); r.y = fmaf(0.9f, e.y, xv);
            r.z = fmaf(0.9f, e.z, xv); r.w = fmaf(0.9f, e.w, xv);
            __stcs(eo + p, r);
        }
    } else {
        // ---------------- GEMM + epilogue path ----------------
        // block handles h-tile of 32 columns, all 32 batch rows.
        __shared__ float xs[32][33];                 // [i][k] (+pad)
        __shared__ __align__(16) float ws[32][32];   // [k][h]

        const int t  = threadIdx.x;
        const int h0 = blockIdx.x * 32;
        const int hx = t & 7;           // which float4 of the 32-h tile
        const int i  = t >> 3;          // batch row 0..31

        float4 acc = make_float4(0.f, 0.f, 0.f, 0.f);

        for (int kt = 0; kt < DD; kt += 32) {
            // x tile: 32 rows x 32 k (coalesced)
            for (int m = t; m < 1024; m += NTHREADS)
                xs[m >> 5][m & 31] = x[(m >> 5) * DD + kt + (m & 31)];
            // w tile: 32 k x 32 h (coalesced)
            for (int m = t; m < 1024; m += NTHREADS)
                ws[m >> 5][m & 31] = w[(kt + (m >> 5)) * HH + h0 + (m & 31)];
            __syncthreads();

            #pragma unroll 8
            for (int k = 0; k < 32; k++) {
                float4 wv = reinterpret_cast<const float4*>(&ws[k][0])[hx];
                float xv = xs[i][k];
                acc.x = fmaf(xv, wv.x, acc.x);
                acc.y = fmaf(xv, wv.y, acc.y);
                acc.z = fmaf(xv, wv.z, acc.z);
                acc.w = fmaf(xv, wv.w, acc.w);
            }
            __syncthreads();
        }

        // epilogue: z = 0.9*u + x@w + b ; out = tanh(z); u_new = z; E_b
        const int h   = h0 + hx * 4;
        const int idx = i * HH + h;
        float4 bv = *reinterpret_cast<const float4*>(&b[h]);
        float4 uv = *reinterpret_cast<const float4*>(&u[idx]);
        float4 z;
        z.x = fmaf(0.9f, uv.x, acc.x + bv.x);
        z.y = fmaf(0.9f, uv.y, acc.y + bv.y);
        z.z = fmaf(0.9f, uv.z, acc.z + bv.z);
        z.w = fmaf(0.9f, uv.w, acc.w + bv.w);

        *reinterpret_cast<float4*>(&out[OFF_UNEW + idx]) = z;

        float4 o;
        o.x = tanhf(z.x); o.y = tanhf(z.y);
        o.z = tanhf(z.z); o.w = tanhf(z.w);
        *reinterpret_cast<float4*>(&out[idx]) = o;

        float4 ev = *reinterpret_cast<const float4*>(&Eb[idx]);
        float4 e;
        e.x = fmaf(0.9f, ev.x, 1.0f);
        e.y = fmaf(0.9f, ev.y, 1.0f);
        e.z = fmaf(0.9f, ev.z, 1.0f);
        e.w = fmaf(0.9f, ev.w, 1.0f);
        *reinterpret_cast<float4*>(&out[OFF_EB + idx]) = e;
    }
}

extern "C" void kernel_launch(void* const* d_in, const int* in_sizes, int n_in,
                              void* d_out, int out_size) {
    const float* x  = (const float*)d_in[0];  // [32,1024]
    const float* w  = (const float*)d_in[1];  // [1024,1024]
    const float* b  = (const float*)d_in[2];  // [1024]
    const float* u  = (const float*)d_in[3];  // [32,1024]
    const float* Ew = (const float*)d_in[4];  // [1,32,1024,1024]
    const float* Eb = (const float*)d_in[5];  // [1,32,1024]
    float* out = (float*)d_out;

    diag_rtrl_fused_kernel<<<GEMM_BLOCKS + STREAM_BLOCKS, NTHREADS>>>(
        x, w, b, u, Ew, Eb, out);
}